// round 13
// baseline (speedup 1.0000x reference)
#include <cuda_runtime.h>
#include <cstdint>

// Problem constants
#define BB   128   // batch
#define INW  256   // input width
#define HH   1024  // hidden
#define NP   512   // pairs per A layer
#define LP   128   // number of (A,B) layer pairs
#define FULLMASK 0xffffffffu

// Per-warp-region trig tables (halo-duplicated, identity-padded):
// offset = k*768 + w*96 + j*32 + l (float4 units)
// entry (w,j,l) = global pair g = 64w - 16 + 3l + j ; OOB -> identity (1,0,1,0)
__device__ float4 g_tA[(LP + 2) * 768];
__device__ float4 g_tB[(LP + 2) * 768];
__device__ float  g_pR[4][BB * HH];         // GEMM partials per K-chunk
__device__ float  g_pI[4][BB * HH];

// ---------------------------------------------------------------------------
// Kernel 1: blocks [0,128) = complex GEMM (K-split x4, N-tiles of 32)
//           blocks [128,256) = per-warp-region trig tables (one block/layer)
// ---------------------------------------------------------------------------
__global__ __launch_bounds__(256) void k1(
    const float* __restrict__ inR, const float* __restrict__ inI,
    const float* __restrict__ wR,  const float* __restrict__ wI,
    const float* __restrict__ A0,  const float* __restrict__ A1,
    const float* __restrict__ B0,  const float* __restrict__ B1)
{
    const int bid = blockIdx.x, tid = threadIdx.x;

    if (bid >= 128) {
        const int k = bid - 128;
        for (int i = tid; i < 768; i += 256) {
            const int w = i / 96, r = i % 96, j = r / 32, l = r % 32;
            const int g = 64 * w - 16 + 3 * l + j;
            float4 va = make_float4(1.f, 0.f, 1.f, 0.f);
            float4 vb = make_float4(1.f, 0.f, 1.f, 0.f);
            if (g >= 0 && g < 512) {
                float c0, s0, c1, s1;
                sincosf(A0[k * 512 + g], &s0, &c0);
                sincosf(A1[k * 512 + g], &s1, &c1);
                va = make_float4(c0, s0, c1, s1);
            }
            if (g >= 0 && g < 511) {
                float c0, s0, c1, s1;
                sincosf(B0[k * 511 + g], &s0, &c0);
                sincosf(B1[k * 511 + g], &s1, &c1);
                vb = make_float4(c0, s0, c1, s1);
            }
            g_tA[k * 768 + i] = va;
            g_tB[k * 768 + i] = vb;
        }
        return;
    }

    // ---- complex GEMM: tile M=128, N=32, K-chunk=64 ----
    const int kc = bid >> 5, nt = bid & 31;
    const int k0 = kc * 64, n0 = nt * 32;

    __shared__ float sXR[32][132], sXI[32][132];
    __shared__ float sWR[32][33],  sWI[32][33];

    float accR[8][2], accI[8][2];
    #pragma unroll
    for (int r = 0; r < 8; r++)
        #pragma unroll
        for (int c = 0; c < 2; c++) { accR[r][c] = 0.f; accI[r][c] = 0.f; }

    const int mi = tid >> 4, ni = tid & 15;
    const int lm = tid & 127, kh = (tid >> 7) * 16;
    const int wn = tid >> 3,  wk = (tid & 7) * 4;

    for (int ks = 0; ks < 64; ks += 32) {
        __syncthreads();
        #pragma unroll
        for (int j = 0; j < 4; j++) {
            const int kk = kh + j * 4;
            float4 vR = *(const float4*)(inR + lm * INW + k0 + ks + kk);
            float4 vI = *(const float4*)(inI + lm * INW + k0 + ks + kk);
            sXR[kk+0][lm] = vR.x; sXR[kk+1][lm] = vR.y;
            sXR[kk+2][lm] = vR.z; sXR[kk+3][lm] = vR.w;
            sXI[kk+0][lm] = vI.x; sXI[kk+1][lm] = vI.y;
            sXI[kk+2][lm] = vI.z; sXI[kk+3][lm] = vI.w;
        }
        {
            float4 vR = *(const float4*)(wR + (n0 + wn) * INW + k0 + ks + wk);
            float4 vI = *(const float4*)(wI + (n0 + wn) * INW + k0 + ks + wk);
            sWR[wk+0][wn] = vR.x; sWR[wk+1][wn] = vR.y;
            sWR[wk+2][wn] = vR.z; sWR[wk+3][wn] = vR.w;
            sWI[wk+0][wn] = vI.x; sWI[wk+1][wn] = vI.y;
            sWI[wk+2][wn] = vI.z; sWI[wk+3][wn] = vI.w;
        }
        __syncthreads();

        #pragma unroll 8
        for (int kk = 0; kk < 32; kk++) {
            float aRv[8], aIv[8], bRv[2], bIv[2];
            *(float4*)&aRv[0] = *(const float4*)&sXR[kk][mi * 8];
            *(float4*)&aRv[4] = *(const float4*)&sXR[kk][mi * 8 + 4];
            *(float4*)&aIv[0] = *(const float4*)&sXI[kk][mi * 8];
            *(float4*)&aIv[4] = *(const float4*)&sXI[kk][mi * 8 + 4];
            bRv[0] = sWR[kk][ni*2]; bRv[1] = sWR[kk][ni*2+1];
            bIv[0] = sWI[kk][ni*2]; bIv[1] = sWI[kk][ni*2+1];
            #pragma unroll
            for (int r = 0; r < 8; r++)
                #pragma unroll
                for (int c = 0; c < 2; c++) {
                    accR[r][c] += aRv[r]*bRv[c] - aIv[r]*bIv[c];
                    accI[r][c] += aRv[r]*bIv[c] + aIv[r]*bRv[c];
                }
        }
    }

    #pragma unroll
    for (int r = 0; r < 8; r++) {
        const int m = mi * 8 + r;
        #pragma unroll
        for (int c = 0; c < 2; c++) {
            g_pR[kc][m * HH + n0 + ni*2 + c] = accR[r][c];
            g_pI[kc][m * HH + n0 + ni*2 + c] = accI[r][c];
        }
    }
}

// ---------------------------------------------------------------------------
// helpers
// ---------------------------------------------------------------------------
__device__ __forceinline__ float4 ldg_v4_pinned(const float4* p) {
    float4 v;
    asm volatile("ld.global.nc.v4.f32 {%0,%1,%2,%3}, [%4];"
                 : "=f"(v.x), "=f"(v.y), "=f"(v.z), "=f"(v.w) : "l"(p));
    return v;
}

__device__ __forceinline__ void sts2_pred(uint32_t addr, int pred, float x, float y) {
    asm volatile("{\n\t"
                 ".reg .pred p;\n\t"
                 "setp.ne.s32 p, %0, 0;\n\t"
                 "@p st.shared.v2.f32 [%1], {%2,%3};\n\t"
                 "}"
                 :: "r"(pred), "r"(addr), "f"(x), "f"(y) : "memory");
}

// one MZI on channels (a,b) given trig T; updates in place
#define MZI(T, AR, AI, BR, BI)                                   \
    {                                                            \
        float pr = (T).x*(AR) - (T).y*(AI);                      \
        float pi = (T).y*(AR) + (T).x*(AI);                      \
        float n0r = (T).z*pr - (T).w*(BI);                       \
        float n0i = (T).z*pi + (T).w*(BR);                       \
        float n1r = (T).z*(BR) - (T).w*pi;                       \
        float n1i = (T).z*(BI) + (T).w*pr;                       \
        (AR) = n0r; (AI) = n0i; (BR) = n1r; (BI) = n1i;          \
    }

// ---------------------------------------------------------------------------
// Kernel 2: Clements mesh — halo-decoupled warps, TWO batch rows per CTA.
// Warp w owns channels [128w,128w+128), works on 192 (halo 32/side, 6/lane).
// 16 layer pairs run shfl-only; every 16 pairs one image-sync per row.
// Trig loads (the L2-bandwidth binder) are shared between both rows.
// ---------------------------------------------------------------------------
__global__ __launch_bounds__(256, 1) void k2(
    const float* __restrict__ stR, const float* __restrict__ stI,
    const float* __restrict__ bR,  const float* __restrict__ bI,
    const float* __restrict__ om,  const float* __restrict__ mb,
    float* __restrict__ out)
{
    const int b0v = blockIdx.x, b1v = blockIdx.x + 64;
    const int t = threadIdx.x;
    const int w = t >> 5, l = t & 31;
    const int c = 128 * w - 32 + 6 * l;        // my 6 channels: c .. c+5

    __shared__ float2 simg[2][2][HH];          // [row][parity][channel]

    const uint32_t imgBase = (uint32_t)__cvta_generic_to_shared(simg);

    // initial state: my 6 channels (clamped), both rows
    float xr[6], xi[6], yr[6], yi[6];
    #pragma unroll
    for (int j = 0; j < 6; j++) {
        int gc = c + j; gc = gc < 0 ? 0 : (gc > HH - 1 ? HH - 1 : gc);
        xr[j] = stR[b0v * HH + gc];
        xi[j] = stI[b0v * HH + gc];
        yr[j] = stR[b1v * HH + gc];
        yi[j] = stI[b1v * HH + gc];
    }

    const int idx0 = w * 96 + l;
    const float4* gA = g_tA;
    const float4* gB = g_tB;

    float4 cA0 = ldg_v4_pinned(gA + idx0);
    float4 cA1 = ldg_v4_pinned(gA + idx0 + 32);
    float4 cA2 = ldg_v4_pinned(gA + idx0 + 64);
    float4 cB0 = ldg_v4_pinned(gB + idx0);
    float4 cB1 = ldg_v4_pinned(gB + idx0 + 32);
    float4 cB2 = ldg_v4_pinned(gB + idx0 + 64);
    int off = 768 + idx0;

    for (int e = 0; e < 8; e++) {
        #pragma unroll 4
        for (int kk = 0; kk < 16; kk++) {
            // prefetch next layer pair's trig (depth-1)
            float4 nA0 = ldg_v4_pinned(gA + off);
            float4 nA1 = ldg_v4_pinned(gA + off + 32);
            float4 nA2 = ldg_v4_pinned(gA + off + 64);
            float4 nB0 = ldg_v4_pinned(gB + off);
            float4 nB1 = ldg_v4_pinned(gB + off + 32);
            float4 nB2 = ldg_v4_pinned(gB + off + 64);
            off += 768;

            // ---- layer A: 3 lane-local MZIs, both rows ----
            MZI(cA0, xr[0], xi[0], xr[1], xi[1]);
            MZI(cA0, yr[0], yi[0], yr[1], yi[1]);
            MZI(cA1, xr[2], xi[2], xr[3], xi[3]);
            MZI(cA1, yr[2], yi[2], yr[3], yi[3]);
            MZI(cA2, xr[4], xi[4], xr[5], xi[5]);
            MZI(cA2, yr[4], yi[4], yr[5], yi[5]);

            // ---- edge B MZI (x5, right neighbor's x0): phase + u, both rows ----
            float p5rx = cB2.x*xr[5] - cB2.y*xi[5];
            float p5ix = cB2.y*xr[5] + cB2.x*xi[5];
            float uxx = cB2.w*p5rx, uyx = cB2.w*p5ix;
            float p5ry = cB2.x*yr[5] - cB2.y*yi[5];
            float p5iy = cB2.y*yr[5] + cB2.x*yi[5];
            float uxy = cB2.w*p5ry, uyy = cB2.w*p5iy;
            float uz = cB2.z;

            // intra-warp exchange (uz shared between rows: 9 shuffles)
            float nb0rx = __shfl_down_sync(FULLMASK, xr[0], 1);
            float nb0ix = __shfl_down_sync(FULLMASK, xi[0], 1);
            float nb0ry = __shfl_down_sync(FULLMASK, yr[0], 1);
            float nb0iy = __shfl_down_sync(FULLMASK, yi[0], 1);
            float luxx = __shfl_up_sync(FULLMASK, uxx, 1);
            float luyx = __shfl_up_sync(FULLMASK, uyx, 1);
            float luxy = __shfl_up_sync(FULLMASK, uxy, 1);
            float luyy = __shfl_up_sync(FULLMASK, uyy, 1);
            float luz  = __shfl_up_sync(FULLMASK, uz, 1);

            // ---- 2 mid B MZIs: lane-local, fill shfl latency, both rows ----
            MZI(cB0, xr[1], xi[1], xr[2], xi[2]);
            MZI(cB0, yr[1], yi[1], yr[2], yi[2]);
            MZI(cB1, xr[3], xi[3], xr[4], xi[4]);
            MZI(cB1, yr[3], yi[3], yr[4], yi[4]);

            // ---- completions: my x5 (right edge), my x0 (left edge) ----
            xr[5] = cB2.z*p5rx - cB2.w*nb0ix;
            xi[5] = cB2.z*p5ix + cB2.w*nb0rx;
            yr[5] = cB2.z*p5ry - cB2.w*nb0iy;
            yi[5] = cB2.z*p5iy + cB2.w*nb0ry;
            {
                float a = luz*xr[0] - luyx;
                float q = luz*xi[0] + luxx;
                xr[0] = a; xi[0] = q;
            }
            {
                float a = luz*yr[0] - luyy;
                float q = luz*yi[0] + luxy;
                yr[0] = a; yi[0] = q;
            }

            cA0 = nA0; cA1 = nA1; cA2 = nA2;
            cB0 = nB0; cB1 = nB1; cB2 = nB2;
        }

        // ---- sync: publish owned channels (both rows), barrier, refresh halo ----
        const uint32_t ib0 = imgBase + (uint32_t)((e & 1) * HH * 8);
        const uint32_t ib1 = imgBase + (uint32_t)(HH * 16 + (e & 1) * HH * 8);
        #pragma unroll
        for (int j = 0; j < 6; j++) {
            const int g = c + j;
            const int pred = ((unsigned)(g - 128 * w) < 128u) ? 1 : 0;
            sts2_pred(ib0 + (uint32_t)(g * 8), pred, xr[j], xi[j]);
            sts2_pred(ib1 + (uint32_t)(g * 8), pred, yr[j], yi[j]);
        }
        __syncthreads();
        if (e < 7) {
            #pragma unroll
            for (int j = 0; j < 6; j++) {
                int gc = c + j; gc = gc < 0 ? 0 : (gc > HH - 1 ? HH - 1 : gc);
                float2 v0 = simg[0][e & 1][gc];
                float2 v1 = simg[1][e & 1][gc];
                xr[j] = v0.x; xi[j] = v0.y;
                yr[j] = v1.x; yi[j] = v1.y;
            }
        }
    }

    // ---- epilogue: thread t handles channels 4t..4t+3, both rows ----
    float4 bR4 = ((const float4*)bR)[t];
    float4 bI4 = ((const float4*)bI)[t];
    float4 om4 = ((const float4*)om)[t];
    float4 mb4 = ((const float4*)mb)[t];
    float oma[4] = {om4.x, om4.y, om4.z, om4.w};
    float mba[4] = {mb4.x, mb4.y, mb4.z, mb4.w};
    float bRa[4] = {bR4.x, bR4.y, bR4.z, bR4.w};
    float bIa[4] = {bI4.x, bI4.y, bI4.z, bI4.w};
    float co4[4], so4[4];
    #pragma unroll
    for (int j = 0; j < 4; j++) sincosf(oma[j], &so4[j], &co4[j]);

    #pragma unroll
    for (int rowsel = 0; rowsel < 2; rowsel++) {
        const int bb = rowsel ? b1v : b0v;
        float ihR[4] = {bRa[0], bRa[1], bRa[2], bRa[3]};
        float ihI[4] = {bIa[0], bIa[1], bIa[2], bIa[3]};
        #pragma unroll
        for (int cc = 0; cc < 4; cc++) {
            float4 pr4 = *(const float4*)&g_pR[cc][bb * HH + 4 * t];
            float4 pi4 = *(const float4*)&g_pI[cc][bb * HH + 4 * t];
            ihR[0] += pr4.x; ihR[1] += pr4.y; ihR[2] += pr4.z; ihR[3] += pr4.w;
            ihI[0] += pi4.x; ihI[1] += pi4.y; ihI[2] += pi4.z; ihI[3] += pi4.w;
        }
        float zr[4], zi[4];
        #pragma unroll
        for (int j = 0; j < 4; j++) {
            float2 v = simg[rowsel][1][4 * t + j];
            float zrr = ihR[j] + co4[j]*v.x - so4[j]*v.y;
            float zii = ihI[j] + so4[j]*v.x + co4[j]*v.y;
            float mag = sqrtf(zrr*zrr + zii*zii);
            float sc  = fmaxf(mag + mba[j], 0.f) / fmaxf(mag, 1e-8f);
            zr[j] = sc*zrr; zi[j] = sc*zii;
        }
        ((float4*)(out + bb * HH))[t]           = make_float4(zr[0], zr[1], zr[2], zr[3]);
        ((float4*)(out + BB * HH + bb * HH))[t] = make_float4(zi[0], zi[1], zi[2], zi[3]);
    }
}

// ---------------------------------------------------------------------------
extern "C" void kernel_launch(void* const* d_in, const int* in_sizes, int n_in,
                              void* d_out, int out_size)
{
    const float* inR = (const float*)d_in[0];
    const float* inI = (const float*)d_in[1];
    const float* stR = (const float*)d_in[2];
    const float* stI = (const float*)d_in[3];
    const float* wR  = (const float*)d_in[4];
    const float* wI  = (const float*)d_in[5];
    const float* bR  = (const float*)d_in[6];
    const float* bI  = (const float*)d_in[7];
    const float* A0  = (const float*)d_in[8];
    const float* A1  = (const float*)d_in[9];
    const float* B0  = (const float*)d_in[10];
    const float* B1  = (const float*)d_in[11];
    const float* om  = (const float*)d_in[12];
    const float* mb  = (const float*)d_in[13];
    float* out = (float*)d_out;

    k1<<<256, 256>>>(inR, inI, wR, wI, A0, A1, B0, B1);
    k2<<<64, 256>>>(stR, stI, bR, bI, om, mb, out);
}

// round 17
// speedup vs baseline: 1.2383x; 1.2383x over previous
#include <cuda_runtime.h>
#include <cstdint>

// Problem constants
#define BB   128   // batch
#define INW  256   // input width
#define HH   1024  // hidden
#define NP   512   // pairs per A layer
#define LP   128   // number of (A,B) layer pairs
#define FULLMASK 0xffffffffu

// Per-warp-region trig tables (halo-duplicated, identity-padded):
// offset = k*768 + w*96 + j*32 + l (float4 units)
// entry (w,j,l) = global pair g = 64w - 16 + 3l + j ; OOB -> identity (1,0,1,0)
// Padded +4 layers: depth-3 prefetch reads up to pair LP+2 (never consumed).
__device__ float4 g_tA[(LP + 4) * 768];
__device__ float4 g_tB[(LP + 4) * 768];
__device__ float  g_pR[4][BB * HH];         // GEMM partials per K-chunk
__device__ float  g_pI[4][BB * HH];

// ---------------------------------------------------------------------------
// Kernel 1: blocks [0,128) = complex GEMM (K-split x4, N-tiles of 32)
//           blocks [128,256) = per-warp-region trig tables (one block/layer)
// ---------------------------------------------------------------------------
__global__ __launch_bounds__(256) void k1(
    const float* __restrict__ inR, const float* __restrict__ inI,
    const float* __restrict__ wR,  const float* __restrict__ wI,
    const float* __restrict__ A0,  const float* __restrict__ A1,
    const float* __restrict__ B0,  const float* __restrict__ B1)
{
    const int bid = blockIdx.x, tid = threadIdx.x;

    if (bid >= 128) {
        const int k = bid - 128;
        for (int i = tid; i < 768; i += 256) {
            const int w = i / 96, r = i % 96, j = r / 32, l = r % 32;
            const int g = 64 * w - 16 + 3 * l + j;
            float4 va = make_float4(1.f, 0.f, 1.f, 0.f);
            float4 vb = make_float4(1.f, 0.f, 1.f, 0.f);
            if (g >= 0 && g < 512) {
                float c0, s0, c1, s1;
                sincosf(A0[k * 512 + g], &s0, &c0);
                sincosf(A1[k * 512 + g], &s1, &c1);
                va = make_float4(c0, s0, c1, s1);
            }
            if (g >= 0 && g < 511) {
                float c0, s0, c1, s1;
                sincosf(B0[k * 511 + g], &s0, &c0);
                sincosf(B1[k * 511 + g], &s1, &c1);
                vb = make_float4(c0, s0, c1, s1);
            }
            g_tA[k * 768 + i] = va;
            g_tB[k * 768 + i] = vb;
        }
        return;
    }

    // ---- complex GEMM: tile M=128, N=32, K-chunk=64 ----
    const int kc = bid >> 5, nt = bid & 31;
    const int k0 = kc * 64, n0 = nt * 32;

    __shared__ float sXR[32][132], sXI[32][132];
    __shared__ float sWR[32][33],  sWI[32][33];

    float accR[8][2], accI[8][2];
    #pragma unroll
    for (int r = 0; r < 8; r++)
        #pragma unroll
        for (int c = 0; c < 2; c++) { accR[r][c] = 0.f; accI[r][c] = 0.f; }

    const int mi = tid >> 4, ni = tid & 15;
    const int lm = tid & 127, kh = (tid >> 7) * 16;
    const int wn = tid >> 3,  wk = (tid & 7) * 4;

    for (int ks = 0; ks < 64; ks += 32) {
        __syncthreads();
        #pragma unroll
        for (int j = 0; j < 4; j++) {
            const int kk = kh + j * 4;
            float4 vR = *(const float4*)(inR + lm * INW + k0 + ks + kk);
            float4 vI = *(const float4*)(inI + lm * INW + k0 + ks + kk);
            sXR[kk+0][lm] = vR.x; sXR[kk+1][lm] = vR.y;
            sXR[kk+2][lm] = vR.z; sXR[kk+3][lm] = vR.w;
            sXI[kk+0][lm] = vI.x; sXI[kk+1][lm] = vI.y;
            sXI[kk+2][lm] = vI.z; sXI[kk+3][lm] = vI.w;
        }
        {
            float4 vR = *(const float4*)(wR + (n0 + wn) * INW + k0 + ks + wk);
            float4 vI = *(const float4*)(wI + (n0 + wn) * INW + k0 + ks + wk);
            sWR[wk+0][wn] = vR.x; sWR[wk+1][wn] = vR.y;
            sWR[wk+2][wn] = vR.z; sWR[wk+3][wn] = vR.w;
            sWI[wk+0][wn] = vI.x; sWI[wk+1][wn] = vI.y;
            sWI[wk+2][wn] = vI.z; sWI[wk+3][wn] = vI.w;
        }
        __syncthreads();

        #pragma unroll 8
        for (int kk = 0; kk < 32; kk++) {
            float aRv[8], aIv[8], bRv[2], bIv[2];
            *(float4*)&aRv[0] = *(const float4*)&sXR[kk][mi * 8];
            *(float4*)&aRv[4] = *(const float4*)&sXR[kk][mi * 8 + 4];
            *(float4*)&aIv[0] = *(const float4*)&sXI[kk][mi * 8];
            *(float4*)&aIv[4] = *(const float4*)&sXI[kk][mi * 8 + 4];
            bRv[0] = sWR[kk][ni*2]; bRv[1] = sWR[kk][ni*2+1];
            bIv[0] = sWI[kk][ni*2]; bIv[1] = sWI[kk][ni*2+1];
            #pragma unroll
            for (int r = 0; r < 8; r++)
                #pragma unroll
                for (int c = 0; c < 2; c++) {
                    accR[r][c] += aRv[r]*bRv[c] - aIv[r]*bIv[c];
                    accI[r][c] += aRv[r]*bIv[c] + aIv[r]*bRv[c];
                }
        }
    }

    #pragma unroll
    for (int r = 0; r < 8; r++) {
        const int m = mi * 8 + r;
        #pragma unroll
        for (int c = 0; c < 2; c++) {
            g_pR[kc][m * HH + n0 + ni*2 + c] = accR[r][c];
            g_pI[kc][m * HH + n0 + ni*2 + c] = accI[r][c];
        }
    }
}

// ---------------------------------------------------------------------------
// helpers
// ---------------------------------------------------------------------------
__device__ __forceinline__ float4 ldg_v4_pinned(const float4* p) {
    float4 v;
    asm volatile("ld.global.nc.v4.f32 {%0,%1,%2,%3}, [%4];"
                 : "=f"(v.x), "=f"(v.y), "=f"(v.z), "=f"(v.w) : "l"(p));
    return v;
}

__device__ __forceinline__ void sts2_pred(uint32_t addr, int pred, float x, float y) {
    asm volatile("{\n\t"
                 ".reg .pred p;\n\t"
                 "setp.ne.s32 p, %0, 0;\n\t"
                 "@p st.shared.v2.f32 [%1], {%2,%3};\n\t"
                 "}"
                 :: "r"(pred), "r"(addr), "f"(x), "f"(y) : "memory");
}

// one MZI on channels (a,b) given trig T; updates in place
#define MZI(T, AR, AI, BR, BI)                                   \
    {                                                            \
        float pr = (T).x*(AR) - (T).y*(AI);                      \
        float pi = (T).y*(AR) + (T).x*(AI);                      \
        float n0r = (T).z*pr - (T).w*(BI);                       \
        float n0i = (T).z*pi + (T).w*(BR);                       \
        float n1r = (T).z*(BR) - (T).w*pi;                       \
        float n1i = (T).z*(BI) + (T).w*pr;                       \
        (AR) = n0r; (AI) = n0i; (BR) = n1r; (BI) = n1i;          \
    }

// one layer-pair body using trig slot S; prefetch pair (k+3) into slot SN
#define BODY(S, SN)                                                        \
    {                                                                      \
        bA0[SN] = ldg_v4_pinned(pAoff);                                    \
        bA1[SN] = ldg_v4_pinned(pAoff + 32);                               \
        bA2[SN] = ldg_v4_pinned(pAoff + 64);                               \
        bB0[SN] = ldg_v4_pinned(pBoff);                                    \
        bB1[SN] = ldg_v4_pinned(pBoff + 32);                               \
        bB2[SN] = ldg_v4_pinned(pBoff + 64);                               \
        pAoff += 768; pBoff += 768;                                        \
        MZI(bA0[S], xr[0], xi[0], xr[1], xi[1]);                           \
        MZI(bA1[S], xr[2], xi[2], xr[3], xi[3]);                           \
        MZI(bA2[S], xr[4], xi[4], xr[5], xi[5]);                           \
        float p5r = bB2[S].x*xr[5] - bB2[S].y*xi[5];                       \
        float p5i = bB2[S].y*xr[5] + bB2[S].x*xi[5];                       \
        float ux = bB2[S].w*p5r, uy = bB2[S].w*p5i, uz = bB2[S].z;         \
        float nb0r = __shfl_down_sync(FULLMASK, xr[0], 1);                 \
        float nb0i = __shfl_down_sync(FULLMASK, xi[0], 1);                 \
        float lux = __shfl_up_sync(FULLMASK, ux, 1);                       \
        float luy = __shfl_up_sync(FULLMASK, uy, 1);                       \
        float luz = __shfl_up_sync(FULLMASK, uz, 1);                       \
        MZI(bB0[S], xr[1], xi[1], xr[2], xi[2]);                           \
        MZI(bB1[S], xr[3], xi[3], xr[4], xi[4]);                           \
        xr[5] = bB2[S].z*p5r - bB2[S].w*nb0i;                              \
        xi[5] = bB2[S].z*p5i + bB2[S].w*nb0r;                              \
        {                                                                  \
            float a_ = luz*xr[0] - luy;                                    \
            float q_ = luz*xi[0] + lux;                                    \
            xr[0] = a_; xi[0] = q_;                                        \
        }                                                                  \
    }

// ---------------------------------------------------------------------------
// Kernel 2: Clements mesh — halo-decoupled warps + depth-3 trig prefetch.
// Warp w owns channels [128w,128w+128), works 192 (halo 32/side, 6/lane).
// 16 layer pairs run shfl-only; every 16 pairs one image-sync.
// Trig pipeline: 4 rotating register slots; body k issues loads for pair
// k+3 into the slot freed at k-1 -> load->use distance ~3 bodies > L2 lat.
// ---------------------------------------------------------------------------
__global__ __launch_bounds__(256, 1) void k2(
    const float* __restrict__ stR, const float* __restrict__ stI,
    const float* __restrict__ bR,  const float* __restrict__ bI,
    const float* __restrict__ om,  const float* __restrict__ mb,
    float* __restrict__ out)
{
    const int b = blockIdx.x, t = threadIdx.x;
    const int w = t >> 5, l = t & 31;
    const int c = 128 * w - 32 + 6 * l;        // my 6 channels: c .. c+5

    __shared__ float2 simg[2][HH];             // double-buffered state image
    const uint32_t imgBase = (uint32_t)__cvta_generic_to_shared(simg);

    // initial state: my 6 channels (clamped)
    float xr[6], xi[6];
    #pragma unroll
    for (int j = 0; j < 6; j++) {
        int gc = c + j; gc = gc < 0 ? 0 : (gc > HH - 1 ? HH - 1 : gc);
        xr[j] = stR[b * HH + gc];
        xi[j] = stI[b * HH + gc];
    }

    const int idx0 = w * 96 + l;

    // 4-slot trig pipeline (slots hold pairs k, k+1, k+2; 4th slot in flight)
    float4 bA0[4], bA1[4], bA2[4], bB0[4], bB1[4], bB2[4];
    #pragma unroll
    for (int s = 0; s < 3; s++) {
        bA0[s] = ldg_v4_pinned(g_tA + s * 768 + idx0);
        bA1[s] = ldg_v4_pinned(g_tA + s * 768 + idx0 + 32);
        bA2[s] = ldg_v4_pinned(g_tA + s * 768 + idx0 + 64);
        bB0[s] = ldg_v4_pinned(g_tB + s * 768 + idx0);
        bB1[s] = ldg_v4_pinned(g_tB + s * 768 + idx0 + 32);
        bB2[s] = ldg_v4_pinned(g_tB + s * 768 + idx0 + 64);
    }
    const float4* pAoff = g_tA + 3 * 768 + idx0;
    const float4* pBoff = g_tB + 3 * 768 + idx0;

    for (int e = 0; e < 8; e++) {
        for (int q = 0; q < 4; q++) {          // 4 x 4 bodies = 16 pairs
            BODY(0, 3);
            BODY(1, 0);
            BODY(2, 1);
            BODY(3, 2);
        }

        // ---- sync: publish owned channels, barrier, refresh halo ----
        const uint32_t ib = imgBase + (uint32_t)((e & 1) * HH * 8);
        #pragma unroll
        for (int j = 0; j < 6; j++) {
            const int g = c + j;
            const int pred = ((unsigned)(g - 128 * w) < 128u) ? 1 : 0;
            sts2_pred(ib + (uint32_t)(g * 8), pred, xr[j], xi[j]);
        }
        __syncthreads();
        if (e < 7) {
            #pragma unroll
            for (int j = 0; j < 6; j++) {
                int gc = c + j; gc = gc < 0 ? 0 : (gc > HH - 1 ? HH - 1 : gc);
                float2 v = simg[e & 1][gc];
                xr[j] = v.x; xi[j] = v.y;
            }
        }
    }

    // ---- epilogue: thread t handles channels 4t..4t+3 from image buf 1 ----
    float hr[4], hi[4];
    #pragma unroll
    for (int j = 0; j < 4; j++) {
        float2 v = simg[1][4 * t + j];
        hr[j] = v.x; hi[j] = v.y;
    }

    float4 bR4 = ((const float4*)bR)[t];
    float4 bI4 = ((const float4*)bI)[t];
    float ihR[4] = {bR4.x, bR4.y, bR4.z, bR4.w};
    float ihI[4] = {bI4.x, bI4.y, bI4.z, bI4.w};
    #pragma unroll
    for (int cc = 0; cc < 4; cc++) {
        float4 pr4 = *(const float4*)&g_pR[cc][b * HH + 4 * t];
        float4 pi4 = *(const float4*)&g_pI[cc][b * HH + 4 * t];
        ihR[0] += pr4.x; ihR[1] += pr4.y; ihR[2] += pr4.z; ihR[3] += pr4.w;
        ihI[0] += pi4.x; ihI[1] += pi4.y; ihI[2] += pi4.z; ihI[3] += pi4.w;
    }
    float4 om4 = ((const float4*)om)[t];
    float4 mb4 = ((const float4*)mb)[t];
    float oma[4] = {om4.x, om4.y, om4.z, om4.w};
    float mba[4] = {mb4.x, mb4.y, mb4.z, mb4.w};

    float zr[4], zi[4];
    #pragma unroll
    for (int j = 0; j < 4; j++) {
        float co, so;
        sincosf(oma[j], &so, &co);
        float zrr = ihR[j] + co*hr[j] - so*hi[j];
        float zii = ihI[j] + so*hr[j] + co*hi[j];
        float mag = sqrtf(zrr*zrr + zii*zii);
        float sc  = fmaxf(mag + mba[j], 0.f) / fmaxf(mag, 1e-8f);
        zr[j] = sc*zrr; zi[j] = sc*zii;
    }
    ((float4*)(out + b * HH))[t]           = make_float4(zr[0], zr[1], zr[2], zr[3]);
    ((float4*)(out + BB * HH + b * HH))[t] = make_float4(zi[0], zi[1], zi[2], zi[3]);
}

// ---------------------------------------------------------------------------
extern "C" void kernel_launch(void* const* d_in, const int* in_sizes, int n_in,
                              void* d_out, int out_size)
{
    const float* inR = (const float*)d_in[0];
    const float* inI = (const float*)d_in[1];
    const float* stR = (const float*)d_in[2];
    const float* stI = (const float*)d_in[3];
    const float* wR  = (const float*)d_in[4];
    const float* wI  = (const float*)d_in[5];
    const float* bR  = (const float*)d_in[6];
    const float* bI  = (const float*)d_in[7];
    const float* A0  = (const float*)d_in[8];
    const float* A1  = (const float*)d_in[9];
    const float* B0  = (const float*)d_in[10];
    const float* B1  = (const float*)d_in[11];
    const float* om  = (const float*)d_in[12];
    const float* mb  = (const float*)d_in[13];
    float* out = (float*)d_out;

    k1<<<256, 256>>>(inR, inI, wR, wI, A0, A1, B0, B1);
    k2<<<128, 256>>>(stR, stI, bR, bI, om, mb, out);
}